// round 11
// baseline (speedup 1.0000x reference)
#include <cuda_runtime.h>
#include <cuda_bf16.h>

// GraphNorm, persistent double-buffered cp.async pipeline, ONE barrier/tile,
// register-held tile (apply never re-reads SMEM).
//   out = a*x + b,  a = gnw*rsqrt(var+eps), b = gnb - a*m*msc
//   var = E[x^2] - 2*(m*msc)*m + (m*msc)^2  (single sweep)
//
// Tile = (graph, 16-col chunk): 512x16 fp32 = 32 KB (64B rows).
// 256 thr/CTA, 3 CTAs/SM, 456 persistent CTAs.
// Key invariant: every thread loads (cp.async), reduces (LDS), and applies
// only its own (row0 + k*64, l4) slots. Therefore:
//   - no barrier needed between wait_group and reduce (self-visibility),
//   - apply works from the registers captured during reduce,
//   - the single partials barrier also fences all tile LDS reads before the
//     buffer becomes the next prefetch target.
// Partials arrays are double-buffered with the tile parity to close the
// fast-warp/slow-warp ps race left by removing the second barrier.

#define TILE_D    16
#define THREADS   256
#define ROW_TILE  512
#define NWARPS    (THREADS / 32)          // 8
#define BUF_ELEMS (ROW_TILE * TILE_D)     // 8192 floats = 32 KB
#define PS_ELEMS  (NWARPS * TILE_D)       // 128 floats
#define TPR       4                       // threads per row (float4)
#define ROWSTEP   (THREADS / TPR)         // 64 rows per pass
#define NPASS     (ROW_TILE / ROWSTEP)    // 8
#define EPSV      1e-6f
#define NCTA      456                     // 3 per SM x 152 SMs

#define SMEM_BYTES ((2*BUF_ELEMS + 4*PS_ELEMS) * sizeof(float))

__device__ __forceinline__ unsigned smem_u32(const void* p) {
    return (unsigned)__cvta_generic_to_shared(p);
}
__device__ __forceinline__ void cp16(unsigned dst, const void* src) {
    asm volatile("cp.async.cg.shared.global [%0], [%1], 16;" :: "r"(dst), "l"(src));
}
__device__ __forceinline__ void cp_commit() {
    asm volatile("cp.async.commit_group;");
}
template <int N> __device__ __forceinline__ void cp_wait() {
    asm volatile("cp.async.wait_group %0;" :: "n"(N));
}

__device__ __forceinline__ void acc4(float4 v, float4& s1, float4& s2) {
    s1.x += v.x; s1.y += v.y; s1.z += v.z; s1.w += v.w;
    s2.x = fmaf(v.x, v.x, s2.x);
    s2.y = fmaf(v.y, v.y, s2.y);
    s2.z = fmaf(v.z, v.z, s2.z);
    s2.w = fmaf(v.w, v.w, s2.w);
}

__global__ __launch_bounds__(THREADS, 3)
void graphnorm_kernel(const float* __restrict__ x,
                      const float* __restrict__ gnw,
                      const float* __restrict__ gnb,
                      const float* __restrict__ msc,
                      const int* __restrict__ bn,
                      float* __restrict__ out,
                      int D, int B)
{
    extern __shared__ float smem[];
    float* buf0 = smem;
    float* buf1 = smem + BUF_ELEMS;
    float* psA  = smem + 2 * BUF_ELEMS;       // ps1/ps2 set A (parity 0)
    float* psB  = psA + 2 * PS_ELEMS;         // ps1/ps2 set B (parity 1)

    const int tid  = threadIdx.x;
    const int wid  = tid >> 5;
    const int lane = tid & 31;
    const int ncc  = D / TILE_D;
    const int ntiles = B * ncc;

    const int l4   = (tid & (TPR - 1)) * 4;   // 0,4,8,12
    const int row0 = tid / TPR;               // 0..63

    int t = blockIdx.x;
    const int stride = gridDim.x;
    if (t >= ntiles) return;

    int pg = 0;
    long long pstart = 0;

#define ISSUE_TILE(dstbuf, XG, CPN)                                           \
    do {                                                                      \
        const float* pp = (XG) + (long long)row0 * D + l4;                    \
        unsigned dd = smem_u32((dstbuf) + row0 * TILE_D + l4);                \
        if ((CPN) == ROW_TILE) {                                              \
            _Pragma("unroll")                                                 \
            for (int it = 0; it < NPASS; ++it) {                              \
                cp16(dd, pp);                                                 \
                pp += (long long)ROWSTEP * D;                                 \
                dd += ROWSTEP * TILE_D * 4;                                   \
            }                                                                 \
        } else {                                                              \
            for (int r = row0; r < (CPN); r += ROWSTEP) {                     \
                cp16(dd, pp);                                                 \
                pp += (long long)ROWSTEP * D;                                 \
                dd += ROWSTEP * TILE_D * 4;                                   \
            }                                                                 \
        }                                                                     \
        cp_commit();                                                          \
    } while (0)

    // ---- prologue: resolve + issue first tile into buf0 ----
    int g = t / ncc;
    while (pg < g) pstart += (long long)bn[pg++];
    int cnt = bn[g];
    int cpn = min(cnt, ROW_TILE);
    const float* xg = x + pstart * (long long)D + (t % ncc) * TILE_D;
    ISSUE_TILE(buf0, xg, cpn);

    int bsel = 0;
    for (;;) {
        const long long cstart = pstart;
        const int   ccnt = cnt, ccpn = cpn;
        const int   cc   = t % ncc;
        const float* cxg = xg;
        float* cb  = bsel ? buf1 : buf0;
        float* ps1 = bsel ? psB  : psA;
        float* ps2 = ps1 + PS_ELEMS;

        // resolve next tile metadata before the wait (off critical path)
        const int tn = t + stride;
        const bool has_next = (tn < ntiles);
        if (has_next) {
            const int gn = tn / ncc;
            while (pg < gn) pstart += (long long)bn[pg++];
            cnt = bn[gn];
            cpn = min(cnt, ROW_TILE);
            xg = x + pstart * (long long)D + (tn % ncc) * TILE_D;
        }

        cp_wait<0>();   // this thread's slots of the current tile are visible
        // Safe to prefetch into the other buffer with NO barrier:
        //  - last tile's reduce reads of that buffer were fenced by the
        //    partials barrier of that tile,
        //  - apply reads came from registers, never from SMEM.
        if (has_next)
            ISSUE_TILE(bsel ? buf0 : buf1, xg, cpn);

        // ---- reduce current tile (capture values in registers) ----
        float4 v[NPASS];
        float4 s1 = make_float4(0.f, 0.f, 0.f, 0.f);
        float4 s2 = make_float4(0.f, 0.f, 0.f, 0.f);
        bool have_regs = (ccpn == ROW_TILE);
        if (have_regs) {
            const float* tp = cb + row0 * TILE_D + l4;
            #pragma unroll
            for (int it = 0; it < NPASS; ++it) {
                v[it] = *(const float4*)(tp + it * ROWSTEP * TILE_D);
                acc4(v[it], s1, s2);
            }
        } else {
            for (int r = row0; r < ccpn; r += ROWSTEP)
                acc4(*(const float4*)(cb + r * TILE_D + l4), s1, s2);
        }
        for (int r = ROW_TILE + row0; r < ccnt; r += ROWSTEP)
            acc4(*(const float4*)(cxg + (long long)r * D + l4), s1, s2);

        #pragma unroll
        for (int off = TPR; off < 32; off <<= 1) {
            s1.x += __shfl_xor_sync(0xffffffffu, s1.x, off);
            s1.y += __shfl_xor_sync(0xffffffffu, s1.y, off);
            s1.z += __shfl_xor_sync(0xffffffffu, s1.z, off);
            s1.w += __shfl_xor_sync(0xffffffffu, s1.w, off);
            s2.x += __shfl_xor_sync(0xffffffffu, s2.x, off);
            s2.y += __shfl_xor_sync(0xffffffffu, s2.y, off);
            s2.z += __shfl_xor_sync(0xffffffffu, s2.z, off);
            s2.w += __shfl_xor_sync(0xffffffffu, s2.w, off);
        }
        if (lane < TPR) {
            *(float4*)(ps1 + wid * TILE_D + lane * 4) = s1;
            *(float4*)(ps2 + wid * TILE_D + lane * 4) = s2;
        }
        __syncthreads();    // the ONLY barrier: partials visible; also fences
                            // all reduce-phase LDS reads of this buffer

        // ---- warp-redundant coeffs, shfl broadcast ----
        float a = 0.f, b = 0.f;
        if (lane < TILE_D) {
            float t1 = 0.f, t2 = 0.f;
            #pragma unroll
            for (int k = 0; k < NWARPS; ++k) {
                t1 += ps1[k * TILE_D + lane];
                t2 += ps2[k * TILE_D + lane];
            }
            const float inv_n = 1.0f / (float)ccnt;
            const float m    = t1 * inv_n;
            const float ex2  = t2 * inv_n;
            const float s    = msc[cc * TILE_D + lane];
            const float ms   = m * s;
            const float var  = ex2 - 2.f * ms * m + ms * ms;
            const float rstd = rsqrtf(var + EPSV);
            a = gnw[cc * TILE_D + lane] * rstd;
            b = gnb[cc * TILE_D + lane] - a * ms;
        }
        float4 av, bv;
        av.x = __shfl_sync(0xffffffffu, a, l4 + 0);
        av.y = __shfl_sync(0xffffffffu, a, l4 + 1);
        av.z = __shfl_sync(0xffffffffu, a, l4 + 2);
        av.w = __shfl_sync(0xffffffffu, a, l4 + 3);
        bv.x = __shfl_sync(0xffffffffu, b, l4 + 0);
        bv.y = __shfl_sync(0xffffffffu, b, l4 + 1);
        bv.z = __shfl_sync(0xffffffffu, b, l4 + 2);
        bv.w = __shfl_sync(0xffffffffu, b, l4 + 3);

        // ---- apply from registers + streaming store ----
        float* og = out + cstart * (long long)D + cc * TILE_D;
        if (have_regs) {
            float* q = og + (long long)row0 * D + l4;
            const long long rstep = (long long)ROWSTEP * D;
            #pragma unroll
            for (int it = 0; it < NPASS; ++it) {
                float4 o;
                o.x = fmaf(av.x, v[it].x, bv.x);
                o.y = fmaf(av.y, v[it].y, bv.y);
                o.z = fmaf(av.z, v[it].z, bv.z);
                o.w = fmaf(av.w, v[it].w, bv.w);
                __stcs((float4*)(q + it * rstep), o);
            }
        } else {
            for (int r = row0; r < ccpn; r += ROWSTEP) {
                float4 w = *(const float4*)(cb + r * TILE_D + l4);
                float4 o;
                o.x = fmaf(av.x, w.x, bv.x);
                o.y = fmaf(av.y, w.y, bv.y);
                o.z = fmaf(av.z, w.z, bv.z);
                o.w = fmaf(av.w, w.w, bv.w);
                __stcs((float4*)(og + (long long)r * D + l4), o);
            }
        }
        for (int r = ROW_TILE + row0; r < ccnt; r += ROWSTEP) {
            float4 w = *(const float4*)(cxg + (long long)r * D + l4);
            float4 o;
            o.x = fmaf(av.x, w.x, bv.x);
            o.y = fmaf(av.y, w.y, bv.y);
            o.z = fmaf(av.z, w.z, bv.z);
            o.w = fmaf(av.w, w.w, bv.w);
            __stcs((float4*)(og + (long long)r * D + l4), o);
        }

        if (!has_next) break;
        t = tn;
        bsel ^= 1;
    }
#undef ISSUE_TILE
}

extern "C" void kernel_launch(void* const* d_in, const int* in_sizes, int n_in,
                              void* d_out, int out_size)
{
    const float* x   = (const float*)d_in[0];
    const float* gnw = (const float*)d_in[1];
    const float* gnb = (const float*)d_in[2];
    const float* msc = (const float*)d_in[3];
    const int*   bn  = (const int*)d_in[4];
    float* out = (float*)d_out;

    const int D = in_sizes[1];     // HIDDEN
    const int B = in_sizes[4];     // NUM_GRAPHS

    cudaFuncSetAttribute(graphnorm_kernel,
                         cudaFuncAttributeMaxDynamicSharedMemorySize,
                         (int)SMEM_BYTES);

    int ntiles = B * (D / TILE_D);
    int grid = ntiles < NCTA ? ntiles : NCTA;
    graphnorm_kernel<<<grid, THREADS, SMEM_BYTES>>>(x, gnw, gnb, msc, bn, out, D, B);
}